// round 1
// baseline (speedup 1.0000x reference)
#include <cuda_runtime.h>
#include <cuda_bf16.h>
#include <cstdint>

// Problem constants
#define BATCH 4
#define SEQ   1024
#define CDIM  2048
#define NHEAD 32
#define HDIM  64
#define QKVN  (3*CDIM)          // 6144
#define MROWS (BATCH*SEQ)       // 4096

// Scratch (device globals: allocation-free rule)
__device__ float g_qkv[(size_t)MROWS * QKVN];          // 4096 x 6144 ; reused as ctx (4096x2048) later
__device__ float g_q[(size_t)BATCH*NHEAD*SEQ*HDIM];
__device__ float g_k[(size_t)BATCH*NHEAD*SEQ*HDIM];
__device__ float g_v[(size_t)BATCH*NHEAD*SEQ*HDIM];

// ---------------------------------------------------------------------------
// SGEMM: C[M,N] = A[M,K] @ B[N,K]^T + bias[N]
// 128x128 block tile, BK=16, 256 threads, 8x8 per-thread register tile.
// ---------------------------------------------------------------------------
__global__ void __launch_bounds__(256) sgemm_tn_bias(
    const float* __restrict__ A, const float* __restrict__ B,
    const float* __restrict__ bias, float* __restrict__ C,
    int M, int N, int K)
{
    __shared__ float As[16][128];
    __shared__ float Bs[16][128];

    const int tid  = threadIdx.x;
    const int row0 = blockIdx.y * 128;
    const int col0 = blockIdx.x * 128;

    const int tr = (tid >> 4) << 3;   // 0..120 step 8
    const int tc = (tid & 15) << 3;

    float acc[8][8];
    #pragma unroll
    for (int i = 0; i < 8; i++)
        #pragma unroll
        for (int j = 0; j < 8; j++) acc[i][j] = 0.f;

    for (int k0 = 0; k0 < K; k0 += 16) {
        // load 128x16 tiles of A and B (as float4, store transposed -> [k][m])
        #pragma unroll
        for (int l = 0; l < 2; l++) {
            int id = tid + l * 256;          // 0..511 (float4 index)
            int r  = id >> 2;
            int c4 = (id & 3) << 2;
            float4 av = *reinterpret_cast<const float4*>(&A[(size_t)(row0 + r) * K + k0 + c4]);
            As[c4 + 0][r] = av.x; As[c4 + 1][r] = av.y;
            As[c4 + 2][r] = av.z; As[c4 + 3][r] = av.w;
            float4 bv = *reinterpret_cast<const float4*>(&B[(size_t)(col0 + r) * K + k0 + c4]);
            Bs[c4 + 0][r] = bv.x; Bs[c4 + 1][r] = bv.y;
            Bs[c4 + 2][r] = bv.z; Bs[c4 + 3][r] = bv.w;
        }
        __syncthreads();

        #pragma unroll
        for (int kk = 0; kk < 16; kk++) {
            float ar[8], br[8];
            #pragma unroll
            for (int i = 0; i < 8; i++) ar[i] = As[kk][tr + i];
            #pragma unroll
            for (int j = 0; j < 8; j++) br[j] = Bs[kk][tc + j];
            #pragma unroll
            for (int i = 0; i < 8; i++)
                #pragma unroll
                for (int j = 0; j < 8; j++)
                    acc[i][j] += ar[i] * br[j];
        }
        __syncthreads();
    }

    #pragma unroll
    for (int i = 0; i < 8; i++) {
        size_t crow = (size_t)(row0 + tr + i) * N + col0 + tc;
        #pragma unroll
        for (int j = 0; j < 8; j++)
            C[crow + j] = acc[i][j] + bias[col0 + tc + j];
    }
}

// ---------------------------------------------------------------------------
// RoPE + transpose: qkv[B*T, 3C] -> q/k/v [B,H,T,hd] with rope on q,k
// rope layout: [T, 16, 2] (cos, sin)
// ---------------------------------------------------------------------------
__global__ void __launch_bounds__(256) rope_transpose(
    const float* __restrict__ qkv, const float* __restrict__ rope,
    float* __restrict__ q, float* __restrict__ k, float* __restrict__ v)
{
    int idx = blockIdx.x * 256 + threadIdx.x;      // < B*T*H*hd = 8388608
    int d = idx & 63;
    int h = (idx >> 6) & 31;
    int t = (idx >> 11) & 1023;
    int b = idx >> 21;

    const float* row = qkv + (size_t)(b * SEQ + t) * QKVN;
    int col = h * HDIM + d;

    float qv, kv;
    if (d < 32) {
        int j = d & 15;
        float cs = rope[(t * 16 + j) * 2 + 0];
        float sn = rope[(t * 16 + j) * 2 + 1];
        if (d < 16) {
            qv = row[col]          * cs - row[col + 16]          * sn;
            kv = row[CDIM + col]   * cs - row[CDIM + col + 16]   * sn;
        } else {
            qv = row[col]          * cs + row[col - 16]          * sn;
            kv = row[CDIM + col]   * cs + row[CDIM + col - 16]   * sn;
        }
    } else {
        qv = row[col];
        kv = row[CDIM + col];
    }
    float vv = row[2 * CDIM + col];

    size_t o = ((size_t)(b * NHEAD + h) * SEQ + t) * HDIM + d;
    q[o] = qv; k[o] = kv; v[o] = vv;
}

// ---------------------------------------------------------------------------
// Causal flash attention, fp32. Block = one (b,h,q-tile of 64 rows).
// 256 threads; thread (rg=tid/16, cg=tid%16) owns a 4x4 micro-tile.
// Writes ctx directly in [B,T,C] layout.
// ---------------------------------------------------------------------------
__global__ void __launch_bounds__(256) attn_kernel(
    const float* __restrict__ Q, const float* __restrict__ K,
    const float* __restrict__ V, float* __restrict__ ctx)
{
    extern __shared__ float sm[];
    float (*qs)[65] = (float(*)[65])(sm);
    float (*ks)[65] = (float(*)[65])(sm + 64 * 65);
    float (*vs)[65] = (float(*)[65])(sm + 2 * 64 * 65);
    float (*ps)[65] = (float(*)[65])(sm + 3 * 64 * 65);

    const int bh = blockIdx.y;              // b*32 + h
    const int b  = bh >> 5;
    const int h  = bh & 31;
    const int qt = blockIdx.x;
    const int q0 = qt * 64;
    const int tid = threadIdx.x;
    const int rg = tid >> 4;                // rows rg*4 .. rg*4+3
    const int cg = tid & 15;                // cols cg*4 .. cg*4+3

    // load Q tile
    const float* Qb = Q + ((size_t)bh * SEQ + q0) * HDIM;
    #pragma unroll
    for (int l2 = 0; l2 < 4; l2++) {
        int id = tid + l2 * 256;            // float4 index 0..1023
        int r  = id >> 4;
        int c4 = (id & 15) << 2;
        float4 v4 = *reinterpret_cast<const float4*>(Qb + r * HDIM + c4);
        qs[r][c4] = v4.x; qs[r][c4 + 1] = v4.y; qs[r][c4 + 2] = v4.z; qs[r][c4 + 3] = v4.w;
    }

    float acc[4][4];
    float mrow[4], lrow[4];
    #pragma unroll
    for (int i = 0; i < 4; i++) {
        mrow[i] = -1e30f; lrow[i] = 0.f;
        #pragma unroll
        for (int j = 0; j < 4; j++) acc[i][j] = 0.f;
    }
    const float scale = 0.125f;   // 1/sqrt(64)

    for (int kt = 0; kt <= qt; kt++) {
        const int k0 = kt * 64;
        const float* Kb = K + ((size_t)bh * SEQ + k0) * HDIM;
        const float* Vb = V + ((size_t)bh * SEQ + k0) * HDIM;

        __syncthreads();   // protect ks/vs/ps from previous iteration readers
        #pragma unroll
        for (int l2 = 0; l2 < 4; l2++) {
            int id = tid + l2 * 256;
            int r  = id >> 4;
            int c4 = (id & 15) << 2;
            float4 k4 = *reinterpret_cast<const float4*>(Kb + r * HDIM + c4);
            ks[r][c4] = k4.x; ks[r][c4 + 1] = k4.y; ks[r][c4 + 2] = k4.z; ks[r][c4 + 3] = k4.w;
            float4 v4 = *reinterpret_cast<const float4*>(Vb + r * HDIM + c4);
            vs[r][c4] = v4.x; vs[r][c4 + 1] = v4.y; vs[r][c4 + 2] = v4.z; vs[r][c4 + 3] = v4.w;
        }
        __syncthreads();

        // S = Q K^T  (4x4 per thread)
        float s[4][4];
        #pragma unroll
        for (int i = 0; i < 4; i++)
            #pragma unroll
            for (int j = 0; j < 4; j++) s[i][j] = 0.f;

        #pragma unroll 8
        for (int d = 0; d < 64; d++) {
            float qv[4], kv[4];
            #pragma unroll
            for (int i = 0; i < 4; i++) qv[i] = qs[rg * 4 + i][d];
            #pragma unroll
            for (int j = 0; j < 4; j++) kv[j] = ks[cg * 4 + j][d];
            #pragma unroll
            for (int i = 0; i < 4; i++)
                #pragma unroll
                for (int j = 0; j < 4; j++)
                    s[i][j] += qv[i] * kv[j];
        }

        const bool diag = (kt == qt);
        #pragma unroll
        for (int i = 0; i < 4; i++)
            #pragma unroll
            for (int j = 0; j < 4; j++) {
                float val = s[i][j] * scale;
                if (diag && (k0 + cg * 4 + j > q0 + rg * 4 + i)) val = -1e30f;
                s[i][j] = val;
            }

        // online softmax update
        #pragma unroll
        for (int i = 0; i < 4; i++) {
            float mx = s[i][0];
            #pragma unroll
            for (int j = 1; j < 4; j++) mx = fmaxf(mx, s[i][j]);
            #pragma unroll
            for (int off = 8; off; off >>= 1)
                mx = fmaxf(mx, __shfl_xor_sync(0xffffffffu, mx, off));

            float mn   = fmaxf(mrow[i], mx);
            float corr = __expf(mrow[i] - mn);
            float rs   = 0.f;
            float p[4];
            #pragma unroll
            for (int j = 0; j < 4; j++) { p[j] = __expf(s[i][j] - mn); rs += p[j]; }
            #pragma unroll
            for (int off = 8; off; off >>= 1)
                rs += __shfl_xor_sync(0xffffffffu, rs, off);

            lrow[i] = lrow[i] * corr + rs;
            mrow[i] = mn;
            #pragma unroll
            for (int j = 0; j < 4; j++) acc[i][j] *= corr;
            #pragma unroll
            for (int j = 0; j < 4; j++) ps[rg * 4 + i][cg * 4 + j] = p[j];
        }
        __syncthreads();

        // acc += P @ V   (out cols = head dims cg*4..cg*4+3)
        #pragma unroll 8
        for (int c = 0; c < 64; c++) {
            float pv[4], vv[4];
            #pragma unroll
            for (int i = 0; i < 4; i++) pv[i] = ps[rg * 4 + i][c];
            #pragma unroll
            for (int j = 0; j < 4; j++) vv[j] = vs[c][cg * 4 + j];
            #pragma unroll
            for (int i = 0; i < 4; i++)
                #pragma unroll
                for (int j = 0; j < 4; j++)
                    acc[i][j] += pv[i] * vv[j];
        }
    }

    // write ctx in [B, T, C] layout
    #pragma unroll
    for (int i = 0; i < 4; i++) {
        int t = q0 + rg * 4 + i;
        float inv = 1.f / lrow[i];
        size_t base = ((size_t)b * SEQ + t) * CDIM + h * HDIM + cg * 4;
        #pragma unroll
        for (int j = 0; j < 4; j++) ctx[base + j] = acc[i][j] * inv;
    }
}

// ---------------------------------------------------------------------------
extern "C" void kernel_launch(void* const* d_in, const int* in_sizes, int n_in,
                              void* d_out, int out_size)
{
    const float* x      = (const float*)d_in[0];
    // d_in[1] = mask (causal, implicit), d_in[2] = index (identity) — unused
    const float* rope   = (const float*)d_in[3];
    const float* Wqkv_w = (const float*)d_in[4];
    const float* Wqkv_b = (const float*)d_in[5];
    const float* out_w  = (const float*)d_in[6];
    const float* out_b  = (const float*)d_in[7];
    float* out = (float*)d_out;

    float *qkv, *q, *k, *v;
    cudaGetSymbolAddress((void**)&qkv, g_qkv);
    cudaGetSymbolAddress((void**)&q,   g_q);
    cudaGetSymbolAddress((void**)&k,   g_k);
    cudaGetSymbolAddress((void**)&v,   g_v);
    float* ctx = qkv;   // reuse qkv scratch for ctx (qkv dead after rope_transpose)

    // 1) QKV projection: [4096,6144] = x @ Wqkv^T + b
    sgemm_tn_bias<<<dim3(QKVN / 128, MROWS / 128), 256>>>(
        x, Wqkv_w, Wqkv_b, qkv, MROWS, QKVN, CDIM);

    // 2) RoPE + transpose to [B,H,T,hd]
    rope_transpose<<<(BATCH * SEQ * NHEAD * HDIM) / 256, 256>>>(qkv, rope, q, k, v);

    // 3) causal attention -> ctx [B,T,C]
    static const int ATTN_SMEM = 4 * 64 * 65 * (int)sizeof(float);  // 66560
    cudaFuncSetAttribute(attn_kernel, cudaFuncAttributeMaxDynamicSharedMemorySize, ATTN_SMEM);
    attn_kernel<<<dim3(SEQ / 64, BATCH * NHEAD), 256, ATTN_SMEM>>>(q, k, v, ctx);

    // 4) output projection: [4096,2048] = ctx @ out_w^T + out_b
    sgemm_tn_bias<<<dim3(CDIM / 128, MROWS / 128), 256>>>(
        ctx, out_w, out_b, out, MROWS, CDIM, CDIM);
}

// round 3
// speedup vs baseline: 2.7798x; 2.7798x over previous
#include <cuda_runtime.h>
#include <cuda_bf16.h>
#include <cstdint>

// Problem constants
#define BATCH 4
#define SEQ   1024
#define CDIM  2048
#define NHEAD 32
#define HDIM  64
#define QKVN  (3*CDIM)          // 6144
#define MROWS (BATCH*SEQ)       // 4096

// Scratch (device globals: allocation-free rule)
__device__ float g_qkv[(size_t)MROWS * QKVN];
__device__ float g_q[(size_t)BATCH*NHEAD*SEQ*HDIM];
__device__ float g_k[(size_t)BATCH*NHEAD*SEQ*HDIM];
__device__ float g_v[(size_t)BATCH*NHEAD*SEQ*HDIM];

// ---------------------------------------------------------------------------
// helpers
// ---------------------------------------------------------------------------
__device__ __forceinline__ uint32_t smem_u32(const void* p) {
    uint32_t a;
    asm("{ .reg .u64 t; cvta.to.shared.u64 t, %1; cvt.u32.u64 %0, t; }" : "=r"(a) : "l"(p));
    return a;
}
#define CP16(dst, src) \
    asm volatile("cp.async.cg.shared.global [%0], [%1], 16;" :: "r"(dst), "l"(src) : "memory")
#define CP_COMMIT() asm volatile("cp.async.commit_group;" ::: "memory")
#define CP_WAIT1()  asm volatile("cp.async.wait_group 1;" ::: "memory")

__device__ __forceinline__ void ldsm_x4(uint32_t a[4], uint32_t addr) {
    asm volatile("ldmatrix.sync.aligned.m8n8.x4.shared.b16 {%0,%1,%2,%3}, [%4];"
        : "=r"(a[0]), "=r"(a[1]), "=r"(a[2]), "=r"(a[3]) : "r"(addr));
}
__device__ __forceinline__ void ldsm_x2(uint32_t a[2], uint32_t addr) {
    asm volatile("ldmatrix.sync.aligned.m8n8.x2.shared.b16 {%0,%1}, [%2];"
        : "=r"(a[0]), "=r"(a[1]) : "r"(addr));
}
__device__ __forceinline__ uint32_t cvt_tf32(uint32_t x) {
    uint32_t r;
    asm("cvt.rna.tf32.f32 %0, %1;" : "=r"(r) : "f"(__uint_as_float(x)));
    return r;
}
__device__ __forceinline__ void mma_tf32(float c[4], const uint32_t a[4], const uint32_t b[2]) {
    asm volatile(
        "mma.sync.aligned.m16n8k8.row.col.f32.tf32.tf32.f32 "
        "{%0,%1,%2,%3}, {%4,%5,%6,%7}, {%8,%9}, {%0,%1,%2,%3};"
        : "+f"(c[0]), "+f"(c[1]), "+f"(c[2]), "+f"(c[3])
        : "r"(a[0]), "r"(a[1]), "r"(a[2]), "r"(a[3]), "r"(b[0]), "r"(b[1]));
}

// ---------------------------------------------------------------------------
// TF32 mma.sync GEMM: C[M,N] = A[M,K] @ B[N,K]^T + bias[N]
// tile 128x128, BK=32, 256 threads (8 warps, 2x4), warp tile 64x32.
// 3-stage cp.async pipeline of raw fp32; SW128-swizzled smem; ldmatrix;
// cvt.rna.tf32 applied to fragments before mma.
// ---------------------------------------------------------------------------
#define BKC 32
#define STAGE_BYTES 32768                  // A 16KB + B 16KB per stage
#define GEMM_SMEM (3 * STAGE_BYTES)        // 98304

__global__ void __launch_bounds__(256) gemm_tf32(
    const float* __restrict__ A, const float* __restrict__ B,
    const float* __restrict__ bias, float* __restrict__ C,
    int M, int N, int K)
{
    extern __shared__ char smem[];
    const uint32_t sb = smem_u32(smem);
    const int tid  = threadIdx.x;
    const int lane = tid & 31;
    const int wid  = tid >> 5;
    const int row0 = blockIdx.y * 128;
    const int col0 = blockIdx.x * 128;
    const int wm = (wid >> 2) * 64;         // warp m offset
    const int wn = (wid & 3) * 32;          // warp n offset

    // cp.async staging pattern: thread covers rows r, r+32, r+64, r+96; 16B col group c
    const int r = tid >> 3;
    const int c = tid & 7;
    const float* aSrc = A + (size_t)(row0 + r) * K + c * 4;
    const float* bSrc = B + (size_t)(col0 + r) * K + c * 4;
    uint32_t dOff[4];
    #pragma unroll
    for (int l = 0; l < 4; l++) {
        int row = r + 32 * l;
        dOff[l] = (uint32_t)(row * 128 + ((c * 16) ^ ((row & 7) << 4)));
    }

    const int nk = K / BKC;

    // ldmatrix per-thread row offsets (byte offset of row start within tile)
    uint32_t aRow[4], bRow[4];
    #pragma unroll
    for (int mi = 0; mi < 4; mi++) aRow[mi] = (uint32_t)((wm + mi * 16 + (lane & 15)) * 128);
    #pragma unroll
    for (int ni = 0; ni < 4; ni++) bRow[ni] = (uint32_t)((wn + ni * 8 + (lane & 7)) * 128);
    const uint32_t xorv = (uint32_t)((lane & 7) << 4);
    const uint32_t aseg = (uint32_t)((lane >> 4) * 16);
    const uint32_t bseg = (uint32_t)(((lane >> 3) & 1) * 16);

    float acc[16][4];
    #pragma unroll
    for (int t = 0; t < 16; t++)
        #pragma unroll
        for (int j = 0; j < 4; j++) acc[t][j] = 0.f;

    // prologue: stages 0,1
    #pragma unroll
    for (int p = 0; p < 2; p++) {
        uint32_t base = sb + p * STAGE_BYTES;
        size_t koff = (size_t)p * BKC;
        #pragma unroll
        for (int l = 0; l < 4; l++) CP16(base + dOff[l],         aSrc + (size_t)l * 32 * K + koff);
        #pragma unroll
        for (int l = 0; l < 4; l++) CP16(base + 16384 + dOff[l], bSrc + (size_t)l * 32 * K + koff);
        CP_COMMIT();
    }

    int sCur = 0, sNext = 2;
    for (int i = 0; i < nk; i++) {
        CP_WAIT1();
        __syncthreads();

        // issue chunk i+2 (or empty group to keep wait semantics)
        if (i + 2 < nk) {
            uint32_t base = sb + sNext * STAGE_BYTES;
            size_t koff = (size_t)(i + 2) * BKC;
            #pragma unroll
            for (int l = 0; l < 4; l++) CP16(base + dOff[l],         aSrc + (size_t)l * 32 * K + koff);
            #pragma unroll
            for (int l = 0; l < 4; l++) CP16(base + 16384 + dOff[l], bSrc + (size_t)l * 32 * K + koff);
        }
        CP_COMMIT();

        const uint32_t aBase = sb + sCur * STAGE_BYTES;
        const uint32_t bBase = aBase + 16384;

        #pragma unroll
        for (int ks = 0; ks < 4; ks++) {
            const uint32_t kb = (uint32_t)(ks * 32);
            uint32_t af[4][4], bf[4][2];
            #pragma unroll
            for (int mi = 0; mi < 4; mi++)
                ldsm_x4(af[mi], aBase + aRow[mi] + ((kb + aseg) ^ xorv));
            #pragma unroll
            for (int ni = 0; ni < 4; ni++)
                ldsm_x2(bf[ni], bBase + bRow[ni] + ((kb + bseg) ^ xorv));
            #pragma unroll
            for (int mi = 0; mi < 4; mi++)
                #pragma unroll
                for (int j = 0; j < 4; j++) af[mi][j] = cvt_tf32(af[mi][j]);
            #pragma unroll
            for (int ni = 0; ni < 4; ni++) {
                bf[ni][0] = cvt_tf32(bf[ni][0]);
                bf[ni][1] = cvt_tf32(bf[ni][1]);
            }
            #pragma unroll
            for (int mi = 0; mi < 4; mi++)
                #pragma unroll
                for (int ni = 0; ni < 4; ni++)
                    mma_tf32(acc[mi * 4 + ni], af[mi], bf[ni]);
        }

        sCur = (sCur + 1) % 3;
        sNext = (sNext + 1) % 3;
    }

    // epilogue: direct register -> gmem with bias
    const int gq = lane >> 2;       // 0..7
    const int qc = lane & 3;        // 0..3
    #pragma unroll
    for (int mi = 0; mi < 4; mi++) {
        #pragma unroll
        for (int ni = 0; ni < 4; ni++) {
            const float* ac = acc[mi * 4 + ni];
            int colb = col0 + wn + ni * 8 + qc * 2;
            float b0 = __ldg(&bias[colb]);
            float b1 = __ldg(&bias[colb + 1]);
            size_t base0 = (size_t)(row0 + wm + mi * 16 + gq) * N + colb;
            C[base0]         = ac[0] + b0;
            C[base0 + 1]     = ac[1] + b1;
            C[base0 + 8 * (size_t)N]     = ac[2] + b0;
            C[base0 + 8 * (size_t)N + 1] = ac[3] + b1;
        }
    }
}

// ---------------------------------------------------------------------------
// RoPE + transpose: qkv[B*T, 3C] -> q/k/v [B,H,T,hd] with rope on q,k
// ---------------------------------------------------------------------------
__global__ void __launch_bounds__(256) rope_transpose(
    const float* __restrict__ qkv, const float* __restrict__ rope,
    float* __restrict__ q, float* __restrict__ k, float* __restrict__ v)
{
    int idx = blockIdx.x * 256 + threadIdx.x;
    int d = idx & 63;
    int h = (idx >> 6) & 31;
    int t = (idx >> 11) & 1023;
    int b = idx >> 21;

    const float* row = qkv + (size_t)(b * SEQ + t) * QKVN;
    int col = h * HDIM + d;

    float qv, kv;
    if (d < 32) {
        int j = d & 15;
        float cs = rope[(t * 16 + j) * 2 + 0];
        float sn = rope[(t * 16 + j) * 2 + 1];
        if (d < 16) {
            qv = row[col]        * cs - row[col + 16]        * sn;
            kv = row[CDIM + col] * cs - row[CDIM + col + 16] * sn;
        } else {
            qv = row[col]        * cs + row[col - 16]        * sn;
            kv = row[CDIM + col] * cs + row[CDIM + col - 16] * sn;
        }
    } else {
        qv = row[col];
        kv = row[CDIM + col];
    }
    float vv = row[2 * CDIM + col];

    size_t o = ((size_t)(b * NHEAD + h) * SEQ + t) * HDIM + d;
    q[o] = qv; k[o] = kv; v[o] = vv;
}

// ---------------------------------------------------------------------------
// Causal flash attention, fp32.
// ---------------------------------------------------------------------------
__global__ void __launch_bounds__(256) attn_kernel(
    const float* __restrict__ Q, const float* __restrict__ K,
    const float* __restrict__ V, float* __restrict__ ctx)
{
    extern __shared__ float sm[];
    float (*qs)[65] = (float(*)[65])(sm);
    float (*ks)[65] = (float(*)[65])(sm + 64 * 65);
    float (*vs)[65] = (float(*)[65])(sm + 2 * 64 * 65);
    float (*ps)[65] = (float(*)[65])(sm + 3 * 64 * 65);

    const int bh = blockIdx.y;
    const int b  = bh >> 5;
    const int h  = bh & 31;
    const int qt = blockIdx.x;
    const int q0 = qt * 64;
    const int tid = threadIdx.x;
    const int rg = tid >> 4;
    const int cg = tid & 15;

    const float* Qb = Q + ((size_t)bh * SEQ + q0) * HDIM;
    #pragma unroll
    for (int l2 = 0; l2 < 4; l2++) {
        int id = tid + l2 * 256;
        int r  = id >> 4;
        int c4 = (id & 15) << 2;
        float4 v4 = *reinterpret_cast<const float4*>(Qb + r * HDIM + c4);
        qs[r][c4] = v4.x; qs[r][c4 + 1] = v4.y; qs[r][c4 + 2] = v4.z; qs[r][c4 + 3] = v4.w;
    }

    float acc[4][4];
    float mrow[4], lrow[4];
    #pragma unroll
    for (int i = 0; i < 4; i++) {
        mrow[i] = -1e30f; lrow[i] = 0.f;
        #pragma unroll
        for (int j = 0; j < 4; j++) acc[i][j] = 0.f;
    }
    const float scale = 0.125f;

    for (int kt = 0; kt <= qt; kt++) {
        const int k0 = kt * 64;
        const float* Kb = K + ((size_t)bh * SEQ + k0) * HDIM;
        const float* Vb = V + ((size_t)bh * SEQ + k0) * HDIM;

        __syncthreads();
        #pragma unroll
        for (int l2 = 0; l2 < 4; l2++) {
            int id = tid + l2 * 256;
            int r  = id >> 4;
            int c4 = (id & 15) << 2;
            float4 k4 = *reinterpret_cast<const float4*>(Kb + r * HDIM + c4);
            ks[r][c4] = k4.x; ks[r][c4 + 1] = k4.y; ks[r][c4 + 2] = k4.z; ks[r][c4 + 3] = k4.w;
            float4 v4 = *reinterpret_cast<const float4*>(Vb + r * HDIM + c4);
            vs[r][c4] = v4.x; vs[r][c4 + 1] = v4.y; vs[r][c4 + 2] = v4.z; vs[r][c4 + 3] = v4.w;
        }
        __syncthreads();

        float s[4][4];
        #pragma unroll
        for (int i = 0; i < 4; i++)
            #pragma unroll
            for (int j = 0; j < 4; j++) s[i][j] = 0.f;

        #pragma unroll 8
        for (int d = 0; d < 64; d++) {
            float qv[4], kv[4];
            #pragma unroll
            for (int i = 0; i < 4; i++) qv[i] = qs[rg * 4 + i][d];
            #pragma unroll
            for (int j = 0; j < 4; j++) kv[j] = ks[cg * 4 + j][d];
            #pragma unroll
            for (int i = 0; i < 4; i++)
                #pragma unroll
                for (int j = 0; j < 4; j++)
                    s[i][j] += qv[i] * kv[j];
        }

        const bool diag = (kt == qt);
        #pragma unroll
        for (int i = 0; i < 4; i++)
            #pragma unroll
            for (int j = 0; j < 4; j++) {
                float val = s[i][j] * scale;
                if (diag && (k0 + cg * 4 + j > q0 + rg * 4 + i)) val = -1e30f;
                s[i][j] = val;
            }

        #pragma unroll
        for (int i = 0; i < 4; i++) {
            float mx = s[i][0];
            #pragma unroll
            for (int j = 1; j < 4; j++) mx = fmaxf(mx, s[i][j]);
            #pragma unroll
            for (int off = 8; off; off >>= 1)
                mx = fmaxf(mx, __shfl_xor_sync(0xffffffffu, mx, off));

            float mn   = fmaxf(mrow[i], mx);
            float corr = __expf(mrow[i] - mn);
            float rs   = 0.f;
            float p[4];
            #pragma unroll
            for (int j = 0; j < 4; j++) { p[j] = __expf(s[i][j] - mn); rs += p[j]; }
            #pragma unroll
            for (int off = 8; off; off >>= 1)
                rs += __shfl_xor_sync(0xffffffffu, rs, off);

            lrow[i] = lrow[i] * corr + rs;
            mrow[i] = mn;
            #pragma unroll
            for (int j = 0; j < 4; j++) acc[i][j] *= corr;
            #pragma unroll
            for (int j = 0; j < 4; j++) ps[rg * 4 + i][cg * 4 + j] = p[j];
        }
        __syncthreads();

        #pragma unroll 8
        for (int cc = 0; cc < 64; cc++) {
            float pv[4], vv[4];
            #pragma unroll
            for (int i = 0; i < 4; i++) pv[i] = ps[rg * 4 + i][cc];
            #pragma unroll
            for (int j = 0; j < 4; j++) vv[j] = vs[cc][cg * 4 + j];
            #pragma unroll
            for (int i = 0; i < 4; i++)
                #pragma unroll
                for (int j = 0; j < 4; j++)
                    acc[i][j] += pv[i] * vv[j];
        }
    }

    #pragma unroll
    for (int i = 0; i < 4; i++) {
        int t = q0 + rg * 4 + i;
        float inv = 1.f / lrow[i];
        size_t base = ((size_t)b * SEQ + t) * CDIM + h * HDIM + cg * 4;
        #pragma unroll
        for (int j = 0; j < 4; j++) ctx[base + j] = acc[i][j] * inv;
    }
}

// ---------------------------------------------------------------------------
extern "C" void kernel_launch(void* const* d_in, const int* in_sizes, int n_in,
                              void* d_out, int out_size)
{
    const float* x      = (const float*)d_in[0];
    const float* rope   = (const float*)d_in[3];
    const float* Wqkv_w = (const float*)d_in[4];
    const float* Wqkv_b = (const float*)d_in[5];
    const float* out_w  = (const float*)d_in[6];
    const float* out_b  = (const float*)d_in[7];
    float* out = (float*)d_out;

    float *qkv, *q, *k, *v;
    cudaGetSymbolAddress((void**)&qkv, g_qkv);
    cudaGetSymbolAddress((void**)&q,   g_q);
    cudaGetSymbolAddress((void**)&k,   g_k);
    cudaGetSymbolAddress((void**)&v,   g_v);
    float* ctx = qkv;

    cudaFuncSetAttribute(gemm_tf32, cudaFuncAttributeMaxDynamicSharedMemorySize, GEMM_SMEM);

    // 1) QKV projection (tf32 tensor cores)
    gemm_tf32<<<dim3(QKVN / 128, MROWS / 128), 256, GEMM_SMEM>>>(
        x, Wqkv_w, Wqkv_b, qkv, MROWS, QKVN, CDIM);

    // 2) RoPE + transpose
    rope_transpose<<<(BATCH * SEQ * NHEAD * HDIM) / 256, 256>>>(qkv, rope, q, k, v);

    // 3) causal attention
    static const int ATTN_SMEM = 4 * 64 * 65 * (int)sizeof(float);
    cudaFuncSetAttribute(attn_kernel, cudaFuncAttributeMaxDynamicSharedMemorySize, ATTN_SMEM);
    attn_kernel<<<dim3(SEQ / 64, BATCH * NHEAD), 256, ATTN_SMEM>>>(q, k, v, ctx);

    // 4) output projection (tf32 tensor cores)
    gemm_tf32<<<dim3(CDIM / 128, MROWS / 128), 256, GEMM_SMEM>>>(
        ctx, out_w, out_b, out, MROWS, CDIM, CDIM);
}